// round 17
// baseline (speedup 1.0000x reference)
#include <cuda_runtime.h>
#include <cuda_bf16.h>

#define DEVI __device__ __forceinline__

constexpr int B_  = 4;
constexpr int H_  = 56;
constexpr int W_  = 56;
constexpr int C_  = 128;
constexpr int NH_ = 4;
constexpr int HD_ = 32;
constexpr int HW_ = H_ * W_;      // 3136
constexpr int M_  = B_ * HW_;     // 12544
constexpr float LOG2E  = 1.4426950408889634f;
constexpr float QSCALE = 0.17677669529663687f; // 32^-0.5

// ---------------- scratch (device globals; referenced from DEVICE code only) --
__device__ __align__(16) unsigned g_Xh[64 * M_], g_Xl[64 * M_];     // x split, k-major [kp][m]
__device__ __align__(16) unsigned g_Wqh[64 * 384], g_Wql[64 * 384]; // w_qkv split [kp][n]
__device__ __align__(16) unsigned g_Wph[64 * 128], g_Wpl[64 * 128]; // w_proj split [kp][n]
__device__ __align__(16) unsigned g_Q[B_ * NH_ * HW_ * 16];         // [b][h][pix][dp] bf16x2 (scaled)
__device__ __align__(16) unsigned g_K[B_ * NH_ * HW_ * 16];
__device__ __align__(16) unsigned g_Vh[B_ * NH_ * HW_ * 16];
__device__ __align__(16) unsigned g_Vl[B_ * NH_ * HW_ * 16];
__device__ __align__(16) unsigned g_Ah[64 * M_], g_Al[64 * M_];     // attn out split, k-major [kp][m]

// ---------------- helpers ---------------------------------------------------
DEVI unsigned pk2(float x, float y) {            // x->low, y->high
    unsigned u;
    asm("cvt.rn.bf16x2.f32 %0, %1, %2;" : "=r"(u) : "f"(y), "f"(x));
    return u;
}
DEVI void bsplit(float x, float &h, float &l) {
    __nv_bfloat16 b = __float2bfloat16(x);
    h = __bfloat162float(b);
    l = x - h;
}
DEVI unsigned prmtb(unsigned a, unsigned b, unsigned sel) {
    unsigned d;
    asm("prmt.b32 %0, %1, %2, %3;" : "=r"(d) : "r"(a), "r"(b), "r"(sel));
    return d;
}
DEVI void mma16(float* c, unsigned a0, unsigned a1, unsigned a2, unsigned a3,
                unsigned b0, unsigned b1) {
    asm("mma.sync.aligned.m16n8k16.row.col.f32.bf16.bf16.f32 "
        "{%0,%1,%2,%3},{%4,%5,%6,%7},{%8,%9},{%0,%1,%2,%3};"
        : "+f"(c[0]), "+f"(c[1]), "+f"(c[2]), "+f"(c[3])
        : "r"(a0), "r"(a1), "r"(a2), "r"(a3), "r"(b0), "r"(b1));
}
DEVI unsigned su32(const void* p) { return (unsigned)__cvta_generic_to_shared(p); }

DEVI void mbar_init(unsigned mb, unsigned cnt) {
    asm volatile("mbarrier.init.shared.b64 [%0], %1;" :: "r"(mb), "r"(cnt) : "memory");
}
DEVI void mbar_expect(unsigned mb, unsigned bytes) {
    asm volatile("mbarrier.arrive.expect_tx.shared.b64 _, [%0], %1;"
                 :: "r"(mb), "r"(bytes) : "memory");
}
DEVI void bulk_cp(unsigned dst, const void* src, unsigned bytes, unsigned mb) {
    asm volatile("cp.async.bulk.shared::cluster.global.mbarrier::complete_tx::bytes "
                 "[%0], [%1], %2, [%3];"
                 :: "r"(dst), "l"(src), "r"(bytes), "r"(mb) : "memory");
}
DEVI void mbar_wait(unsigned mb, unsigned parity) {
    asm volatile(
        "{\n\t"
        ".reg .pred P;\n\t"
        "WL%=: \n\t"
        "mbarrier.try_wait.parity.acquire.cta.shared::cta.b64 P, [%0], %1, 0x989680;\n\t"
        "@P bra WD%=;\n\t"
        "bra WL%=;\n\t"
        "WD%=: \n\t"
        "}"
        :: "r"(mb), "r"(parity) : "memory");
}

// ---------------------------------------------------------------------------
// Prepass: split x / w_qkv / w_proj into hi/lo bf16x2, k-major layout.
// ---------------------------------------------------------------------------
__global__ void __launch_bounds__(256) prepass(const float* __restrict__ x,
                                               const float* __restrict__ wq,
                                               const float* __restrict__ wp)
{
    const int bx = blockIdx.x, tid = threadIdx.x;
    if (bx < 196) {
        __shared__ float xs[64][129];
        const int m0 = bx * 64;
        #pragma unroll
        for (int i = 0; i < 8; i++) {
            const int f = tid + i * 256;
            const int row = f >> 5, c4 = (f & 31) * 4;
            const float4 v = *(const float4*)(x + (size_t)(m0 + row) * 128 + c4);
            xs[row][c4 + 0] = v.x; xs[row][c4 + 1] = v.y;
            xs[row][c4 + 2] = v.z; xs[row][c4 + 3] = v.w;
        }
        __syncthreads();
        #pragma unroll
        for (int i = 0; i < 16; i++) {
            const int u = tid + i * 256;
            const int m = u & 63, kp = u >> 6;
            float ha, la, hb, lb;
            bsplit(xs[m][2 * kp], ha, la);
            bsplit(xs[m][2 * kp + 1], hb, lb);
            g_Xh[kp * M_ + m0 + m] = pk2(ha, hb);
            g_Xl[kp * M_ + m0 + m] = pk2(la, lb);
        }
    } else if (bx == 196) {
        for (int u = tid; u < 64 * 384; u += 256) {
            const int n = u % 384, kp = u / 384;
            float ha, la, hb, lb;
            bsplit(wq[(2 * kp) * 384 + n], ha, la);
            bsplit(wq[(2 * kp + 1) * 384 + n], hb, lb);
            g_Wqh[u] = pk2(ha, hb);
            g_Wql[u] = pk2(la, lb);
        }
    } else {
        for (int u = tid; u < 64 * 128; u += 256) {
            const int n = u % 128, kp = u / 128;
            float ha, la, hb, lb;
            bsplit(wp[(2 * kp) * 128 + n], ha, la);
            bsplit(wp[(2 * kp + 1) * 128 + n], hb, lb);
            g_Wph[u] = pk2(ha, hb);
            g_Wpl[u] = pk2(la, lb);
        }
    }
}

// ---------------------------------------------------------------------------
// GEMM: block tile 64x128, BK=16, 3-stage ring, cp.async.bulk (UBLKCP) DMA.
// Per stage: 32 bulk row-copies (A: 2x8x256B, B: 2x8x512B = 12288B) issued by
// thread 0 into padded smem rows; completion = 1 mbarrier expect_tx/stage.
// This removes the 768-LDGSTS/stage issue serialization (8 cyc/op/SMSP) that
// bound round-16. Strides 72/136 == 8 mod 32 -> fragment LDS conflict-free.
// ---------------------------------------------------------------------------
constexpr int STGU = 3328;               // uints per stage

template<int N, bool QKV>
__global__ void __launch_bounds__(256, 3) gemm_pk(const float* __restrict__ bias,
                                                  float* __restrict__ Cout)
{
    __shared__ __align__(16) unsigned S3[3][STGU];   // 39936 B
    __shared__ __align__(8)  unsigned long long mbar[3];

    const unsigned* __restrict__ AH = QKV ? g_Xh : g_Ah;
    const unsigned* __restrict__ AL = QKV ? g_Xl : g_Al;
    const unsigned* __restrict__ BH = QKV ? g_Wqh : g_Wph;
    const unsigned* __restrict__ BL = QKV ? g_Wql : g_Wpl;

    const int tid  = threadIdx.x;
    const int lane = tid & 31, wid = tid >> 5;
    const int g = lane >> 2, tg = lane & 3;
    const int wm = wid >> 2, wn = wid & 3;
    const int m0 = blockIdx.x * 64, n0 = blockIdx.y * 128;

    if (tid == 0) {
        #pragma unroll
        for (int i = 0; i < 3; i++) mbar_init(su32(&mbar[i]), 1u);
    }
    __syncthreads();

    auto issue = [&](int stage) {        // tid 0 only
        const int bi = stage % 3;
        const unsigned mb = su32(&mbar[bi]);
        const unsigned sb = su32(&S3[bi][0]);
        mbar_expect(mb, 12288u);
        #pragma unroll
        for (int arr = 0; arr < 2; arr++) {
            const unsigned* sA = (arr ? AL : AH) + (size_t)(stage * 8) * M_ + m0;
            const unsigned* sB = (arr ? BL : BH) + (size_t)(stage * 8) * N + n0;
            #pragma unroll
            for (int r = 0; r < 8; r++) {
                bulk_cp(sb + (arr * 576 + r * 72) * 4u,  sA + (size_t)r * M_, 256u, mb);
                bulk_cp(sb + (1152 + arr * 1088 + r * 136) * 4u, sB + (size_t)r * N, 512u, mb);
            }
        }
    };

    if (tid == 0) { issue(0); issue(1); }

    float acc[2][4][4];
    #pragma unroll
    for (int i = 0; i < 2; i++)
        #pragma unroll
        for (int j = 0; j < 4; j++)
            #pragma unroll
            for (int e = 0; e < 4; e++) acc[i][j][e] = 0.0f;

    #pragma unroll 1
    for (int s = 0; s < 8; s++) {
        mbar_wait(su32(&mbar[s % 3]), (unsigned)((s / 3) & 1));
        __syncthreads();                  // all done with compute(s-1): buf (s+2)%3 reusable
        if (s + 2 < 8 && tid == 0) issue(s + 2);

        const unsigned* sb = S3[s % 3];
        unsigned bh0[4], bh1[4], bl0[4], bl1[4];
        #pragma unroll
        for (int na = 0; na < 4; na++) {
            const int n = wn * 32 + na * 8 + g;
            bh0[na] = sb[1152 + tg * 136 + n];        bh1[na] = sb[1152 + (tg + 4) * 136 + n];
            bl0[na] = sb[2240 + tg * 136 + n];        bl1[na] = sb[2240 + (tg + 4) * 136 + n];
        }
        #pragma unroll
        for (int ma = 0; ma < 2; ma++) {
            const int m = wm * 32 + ma * 16 + g;
            const unsigned ah0 = sb[tg * 72 + m],           ah1 = sb[tg * 72 + m + 8];
            const unsigned ah2 = sb[(tg + 4) * 72 + m],     ah3 = sb[(tg + 4) * 72 + m + 8];
            const unsigned al0 = sb[576 + tg * 72 + m],     al1 = sb[576 + tg * 72 + m + 8];
            const unsigned al2 = sb[576 + (tg + 4) * 72 + m], al3 = sb[576 + (tg + 4) * 72 + m + 8];
            #pragma unroll
            for (int na = 0; na < 4; na++)
                mma16(acc[ma][na], ah0, ah1, ah2, ah3, bh0[na], bh1[na]);
            #pragma unroll
            for (int na = 0; na < 4; na++)
                mma16(acc[ma][na], ah0, ah1, ah2, ah3, bl0[na], bl1[na]);
            #pragma unroll
            for (int na = 0; na < 4; na++)
                mma16(acc[ma][na], al0, al1, al2, al3, bh0[na], bh1[na]);
        }
    }

    // ---- epilogue ----
    #pragma unroll
    for (int ma = 0; ma < 2; ma++) {
        #pragma unroll
        for (int half = 0; half < 2; half++) {
            const int m = m0 + wm * 32 + ma * 16 + g + half * 8;
            #pragma unroll
            for (int na = 0; na < 4; na++) {
                const int nl = wn * 32 + na * 8 + tg * 2;
                const float2 bv = *(const float2*)&bias[n0 + nl];
                float o0 = acc[ma][na][half * 2 + 0] + bv.x;
                float o1 = acc[ma][na][half * 2 + 1] + bv.y;
                if (QKV) {
                    const int which = n0 >> 7;          // 0=q,1=k,2=v
                    const int bb  = m / HW_;
                    const int pix = m - bb * HW_;
                    const unsigned idx =
                        (unsigned)(((bb * NH_ + wn) * HW_ + pix) * 16 + na * 4 + tg);
                    if (which == 0) {
                        g_Q[idx] = pk2(o0 * (QSCALE * LOG2E), o1 * (QSCALE * LOG2E));
                    } else if (which == 1) {
                        g_K[idx] = pk2(o0, o1);
                    } else {
                        float h0, l0, h1, l1;
                        bsplit(o0, h0, l0); bsplit(o1, h1, l1);
                        g_Vh[idx] = pk2(h0, h1);
                        g_Vl[idx] = pk2(l0, l1);
                    }
                } else {
                    *(float2*)&Cout[(size_t)m * 128 + nl] = make_float2(o0, o1);
                }
            }
        }
    }
}

// ---------------------------------------------------------------------------
// Tensor-core neighborhood attention, per-warp ROW-WINDOW restriction.
// (unchanged from round 16)
// ---------------------------------------------------------------------------
__global__ void __launch_bounds__(128) attn_tc(const float* __restrict__ rpb)
{
    __shared__ unsigned Kp[16][200];       // 12800 B
    __shared__ unsigned Vph[98][40];       // 15680 B
    __shared__ unsigned Vpl[98][40];       // 15680 B
    __shared__ float bs[169];              //   676 B   (total 44836)

    const int b  = blockIdx.z;
    const int h  = blockIdx.y;
    const int i0 = (blockIdx.x / 7) * 8;
    const int j0 = (blockIdx.x % 7) * 8;
    const int ki0 = min(max(i0 - 3, 0), H_ - 7);
    const int kj0 = min(max(j0 - 3, 0), W_ - 7);
    const int tid = threadIdx.x, lane = tid & 31, w = tid >> 5;
    const int g = lane >> 2, tg = lane & 3;

    const size_t hb = (size_t)(b * NH_ + h) * HW_ * 16;
    const unsigned* qbp = g_Q + hb;
    const unsigned* kbp = g_K + hb;
    const unsigned* vhp = g_Vh + hb;
    const unsigned* vlp = g_Vl + hb;

    for (int x = tid; x < 169; x += 128) bs[x] = rpb[h * 169 + x] * LOG2E;

    // ---- K tile: 196 union keys, coords clamped (invalid masked later) ----
    for (int key = tid; key < 196; key += 128) {
        const int gi = min(ki0 + key / 14, H_ - 1);
        const int gj = min(kj0 + key % 14, W_ - 1);
        const uint4* p = (const uint4*)(kbp + (size_t)(gi * W_ + gj) * 16);
        #pragma unroll
        for (int t = 0; t < 4; t++) {
            const uint4 u = p[t];
            Kp[4 * t + 0][key] = u.x;
            Kp[4 * t + 1][key] = u.y;
            Kp[4 * t + 2][key] = u.z;
            Kp[4 * t + 3][key] = u.w;
        }
    }

    // ---- V tile: 98 key-pairs x 16 dp, key-pair transpose via PRMT ----
    #pragma unroll 1
    for (int it = 0; it < 13; it++) {
        const int idx = it * 128 + tid;
        if (idx < 1568) {
            const int e  = idx & 15;
            const int kp = idx >> 4;
            const int k0 = 2 * kp, k1 = k0 + 1;
            const int gi0 = min(ki0 + k0 / 14, H_ - 1), gj0 = min(kj0 + k0 % 14, W_ - 1);
            const int gi1 = min(ki0 + k1 / 14, H_ - 1), gj1 = min(kj0 + k1 % 14, W_ - 1);
            const size_t o0 = (size_t)(gi0 * W_ + gj0) * 16 + e;
            const size_t o1 = (size_t)(gi1 * W_ + gj1) * 16 + e;
            const unsigned u0h = vhp[o0], u1h = vhp[o1];
            const unsigned u0l = vlp[o0], u1l = vlp[o1];
            *(uint2*)&Vph[kp][2 * e] = make_uint2(prmtb(u0h, u1h, 0x5410u),
                                                  prmtb(u0h, u1h, 0x7632u));
            *(uint2*)&Vpl[kp][2 * e] = make_uint2(prmtb(u0l, u1l, 0x5410u),
                                                  prmtb(u0l, u1l, 0x7632u));
        }
    }

    // ---- Q fragments ----
    const int qi0 = i0 + 2 * w, qi1 = qi0 + 1;
    const int qj  = j0 + g;
    const int qpix0 = qi0 * W_ + qj;
    const int qpix1 = qi1 * W_ + qj;
    unsigned aq[2][4];
    #pragma unroll
    for (int kc = 0; kc < 2; kc++) {
        aq[kc][0] = qbp[(size_t)qpix0 * 16 + kc * 8 + tg];
        aq[kc][1] = qbp[(size_t)qpix1 * 16 + kc * 8 + tg];
        aq[kc][2] = qbp[(size_t)qpix0 * 16 + kc * 8 + tg + 4];
        aq[kc][3] = qbp[(size_t)qpix1 * 16 + kc * 8 + tg + 4];
    }
    __syncthreads();

    // ---- per-warp row window ----
    const int siA = min(max(qi0 - 3, 0), H_ - 7);
    const int siB = min(max(qi1 - 3, 0), H_ - 7);
    const int rb  = siA - ki0;           // 0..6
    const int d1  = siB - siA;           // 0 or 1
    const int rb14 = rb * 14;

    // ---- S = Q K^T over 112 padded cols (14 n-atoms) ----
    float S[14][4];
    #pragma unroll
    for (int na = 0; na < 14; na++)
        #pragma unroll
        for (int e = 0; e < 4; e++) S[na][e] = 0.0f;

    #pragma unroll
    for (int kc = 0; kc < 2; kc++) {
        #pragma unroll
        for (int na = 0; na < 14; na++) {
            const unsigned b0 = Kp[kc * 8 + tg][rb14 + na * 8 + g];
            const unsigned b1 = Kp[kc * 8 + tg + 4][rb14 + na * 8 + g];
            mma16(S[na], aq[kc][0], aq[kc][1], aq[kc][2], aq[kc][3], b0, b1);
        }
    }

    // ---- masked softmax + pack P (A-frag layout) ----
    const int c0q = min(max(qj - 3, 0), W_ - 7) - kj0;
    const int cbA = (ki0 + rb - qi0 + 6) * 13 + (kj0 - qj + 6);
    const int cbB = (ki0 + rb - qi1 + 6) * 13 + (kj0 - qj + 6);

    float sum0 = 0.0f, sum1 = 0.0f;
    unsigned Ph[7][4], Pl[7][4];
    #pragma unroll
    for (int kc = 0; kc < 7; kc++) {
        float p[2][4];
        #pragma unroll
        for (int sub = 0; sub < 2; sub++) {
            const int na = 2 * kc + sub;
            #pragma unroll
            for (int e = 0; e < 2; e++) {
                const int c  = na * 8 + tg * 2 + e;   // local slot 0..111
                const int r  = c / 14;                 // local row 0..7
                const int cc = c - r * 14;             // union col 0..13
                const int t  = r * 13 + cc;
                const bool okc = ((unsigned)(cc - c0q) < 7u);
                const bool okA = (r < 7) && okc;
                const bool okB = ((unsigned)(r - d1) < 7u) && okc;
                const float bA = bs[okA ? (cbA + t) : 0];
                const float bB = bs[okB ? (cbB + t) : 0];
                const float pA = okA ? exp2f(S[na][e] + bA) : 0.0f;
                const float pB = okB ? exp2f(S[na][2 + e] + bB) : 0.0f;
                sum0 += pA; sum1 += pB;
                p[sub][e] = pA; p[sub][2 + e] = pB;
            }
        }
        float h0, l0, h1, l1;
        bsplit(p[0][0], h0, l0); bsplit(p[0][1], h1, l1);
        Ph[kc][0] = pk2(h0, h1); Pl[kc][0] = pk2(l0, l1);
        bsplit(p[0][2], h0, l0); bsplit(p[0][3], h1, l1);
        Ph[kc][1] = pk2(h0, h1); Pl[kc][1] = pk2(l0, l1);
        bsplit(p[1][0], h0, l0); bsplit(p[1][1], h1, l1);
        Ph[kc][2] = pk2(h0, h1); Pl[kc][2] = pk2(l0, l1);
        bsplit(p[1][2], h0, l0); bsplit(p[1][3], h1, l1);
        Ph[kc][3] = pk2(h0, h1); Pl[kc][3] = pk2(l0, l1);
    }
    sum0 += __shfl_xor_sync(0xffffffffu, sum0, 1);
    sum0 += __shfl_xor_sync(0xffffffffu, sum0, 2);
    sum1 += __shfl_xor_sync(0xffffffffu, sum1, 1);
    sum1 += __shfl_xor_sync(0xffffffffu, sum1, 2);
    const float inv0 = 1.0f / sum0;
    const float inv1 = 1.0f / sum1;

    // ---- O = P V over the warp's 112 keys (7 k-chunks, 3-pass) ----
    const int kp0 = rb * 7;
    float o[4][4];
    #pragma unroll
    for (int na = 0; na < 4; na++)
        #pragma unroll
        for (int e = 0; e < 4; e++) o[na][e] = 0.0f;

    #pragma unroll
    for (int kc = 0; kc < 7; kc++) {
        unsigned vh0[4], vh1[4], vl0[4], vl1[4];
        #pragma unroll
        for (int na = 0; na < 4; na++) {
            vh0[na] = Vph[kp0 + kc * 8 + tg][na * 8 + g];
            vh1[na] = Vph[kp0 + kc * 8 + tg + 4][na * 8 + g];
            vl0[na] = Vpl[kp0 + kc * 8 + tg][na * 8 + g];
            vl1[na] = Vpl[kp0 + kc * 8 + tg + 4][na * 8 + g];
        }
        #pragma unroll
        for (int na = 0; na < 4; na++)
            mma16(o[na], Ph[kc][0], Ph[kc][1], Ph[kc][2], Ph[kc][3], vh0[na], vh1[na]);
        #pragma unroll
        for (int na = 0; na < 4; na++)
            mma16(o[na], Ph[kc][0], Ph[kc][1], Ph[kc][2], Ph[kc][3], vl0[na], vl1[na]);
        #pragma unroll
        for (int na = 0; na < 4; na++)
            mma16(o[na], Pl[kc][0], Pl[kc][1], Pl[kc][2], Pl[kc][3], vh0[na], vh1[na]);
    }

    // ---- write attn output pre-split, k-major [kp][m] for proj GEMM ----
    const int mm0 = b * HW_ + qpix0;
    const int mm1 = b * HW_ + qpix1;
    #pragma unroll
    for (int na = 0; na < 4; na++) {
        const int kp = h * 16 + na * 4 + tg;
        float h0, l0, h1, l1;
        bsplit(o[na][0] * inv0, h0, l0); bsplit(o[na][1] * inv0, h1, l1);
        g_Ah[kp * M_ + mm0] = pk2(h0, h1);
        g_Al[kp * M_ + mm0] = pk2(l0, l1);
        bsplit(o[na][2] * inv1, h0, l0); bsplit(o[na][3] * inv1, h1, l1);
        g_Ah[kp * M_ + mm1] = pk2(h0, h1);
        g_Al[kp * M_ + mm1] = pk2(l0, l1);
    }
}

// ---------------------------------------------------------------------------
extern "C" void kernel_launch(void* const* d_in, const int* in_sizes, int n_in,
                              void* d_out, int out_size)
{
    const float* x      = (const float*)d_in[0];
    const float* w_qkv  = (const float*)d_in[1];
    const float* b_qkv  = (const float*)d_in[2];
    const float* rpb    = (const float*)d_in[3];
    const float* w_proj = (const float*)d_in[4];
    const float* b_proj = (const float*)d_in[5];
    float* out = (float*)d_out;

    prepass<<<198, 256>>>(x, w_qkv, w_proj);
    gemm_pk<384, true ><<<dim3(196, 3), 256>>>(b_qkv, nullptr);
    attn_tc<<<dim3(49, NH_, B_), 128>>>(rpb);
    gemm_pk<128, false><<<dim3(196, 1), 256>>>(b_proj, out);
}